// round 15
// baseline (speedup 1.0000x reference)
#include <cuda_runtime.h>
#include <stdint.h>
#include <cstdio>
#include <cstring>
#include <cstdlib>

#define NN 10000
#define EMAX 320000

// ---------------- device scratch ----------------
// RULE (bug fixed this round): these symbols are ONLY referenced inside device
// code. Passing a __device__ symbol as a kernel argument from host code yields
// the host shadow address (GPU-writable via ATS on GB300) -> silent data loss.
__device__ int g_is64;
__device__ int g_rows[EMAX];
__device__ int g_cols[EMAX];
__device__ int g_deg[NN];
__device__ int g_off[NN + 1];
__device__ int g_cursor[NN];
__device__ int g_srclist[EMAX + NN];
__device__ __align__(16) float g_h[NN * 32];
__device__ __align__(16) float g_es[NN * 8];
__device__ __align__(16) float g_ed[NN * 8];
__device__ __align__(16) float g_x3[NN * 32];
__device__ __align__(16) float g_x4[NN * 16];
__device__ __align__(16) float g_x6[NN * 8];
__device__ __align__(16) unsigned g_bitmap[((size_t)NN * NN) / 32];  // 12.5 MB
__device__ int g_degc[NN];
__device__ __align__(16) float g_agg[NN * 8];

// ---------------- edge decode ----------------
__global__ void k_detect(const void* ei) {
    const int* p = (const int*)ei;
    int allz = 1;
    for (int w = 1; w < 96; w += 2) allz &= (p[w] == 0) ? 1 : 0;
    g_is64 = allz;   // int64 data has zero high words (ids < 10000)
}

__global__ void k_decode(const void* __restrict__ ei, int E) {
    int e = blockIdx.x * blockDim.x + threadIdx.x;
    if (e >= E) return;
    if (g_is64) {
        const long long* q = (const long long*)ei;
        g_rows[e] = (int)q[e];
        g_cols[e] = (int)q[E + e];
    } else {
        const int* q = (const int*)ei;
        g_rows[e] = q[e];
        g_cols[e] = q[E + e];
    }
}

// ---------------- CSR-by-dst build (counting sort) ----------------
__global__ void k_initdeg() {
    int i = blockIdx.x * blockDim.x + threadIdx.x;
    if (i < NN) g_deg[i] = 1;   // appended self-loop
}

__global__ void k_hist(int E) {
    int e = blockIdx.x * blockDim.x + threadIdx.x;
    if (e < E) atomicAdd(&g_deg[g_cols[e]], 1);
}

__global__ void k_scan() {
    __shared__ int sh[1024];
    int tid = threadIdx.x;
    const int CH = (NN + 1023) / 1024;
    int base = tid * CH;
    int s = 0;
    for (int i = 0; i < CH; i++) {
        int j = base + i;
        if (j < NN) s += g_deg[j];
    }
    sh[tid] = s;
    __syncthreads();
    for (int ofs = 1; ofs < 1024; ofs <<= 1) {
        int v = (tid >= ofs) ? sh[tid - ofs] : 0;
        __syncthreads();
        sh[tid] += v;
        __syncthreads();
    }
    int run = (tid == 0) ? 0 : sh[tid - 1];
    for (int i = 0; i < CH; i++) {
        int j = base + i;
        if (j < NN) {
            g_off[j] = run;
            g_cursor[j] = run;
            run += g_deg[j];
        }
    }
    if (tid == 1023) g_off[NN] = sh[1023];
}

__global__ void k_scatter(int E) {
    int i = blockIdx.x * blockDim.x + threadIdx.x;
    if (i >= E + NN) return;
    int r, c;
    if (i < E) { r = g_rows[i]; c = g_cols[i]; }
    else       { r = i - E;     c = r; }       // self-loop
    int p = atomicAdd(&g_cursor[c], 1);
    g_srclist[p] = r;
}

// ---------------- GAT transform: h = x@W, e_src/e_dst einsums ----------------
template <int L>
__global__ void k_transform(const float* __restrict__ xext,
                            const float* __restrict__ W,
                            const float* __restrict__ asrc,
                            const float* __restrict__ adst) {
    constexpr int IN = (L == 1) ? 10 : (L == 2) ? 32 : 16;
    constexpr int H  = (L == 1) ? 8  : (L == 2) ? 4  : 2;
    constexpr int HC = H * 4;
    const float* x = (L == 1) ? xext : (L == 2) ? g_x3 : g_x4;   // device symbols, device-side

    __shared__ float sW[IN * HC];
    __shared__ float sas[HC], sad[HC];
    for (int t = threadIdx.x; t < IN * HC; t += blockDim.x) sW[t] = W[t];
    for (int t = threadIdx.x; t < HC; t += blockDim.x) { sas[t] = asrc[t]; sad[t] = adst[t]; }
    __syncthreads();
    int i = blockIdx.x * blockDim.x + threadIdx.x;
    if (i >= NN) return;
    float xi[IN];
#pragma unroll
    for (int k = 0; k < IN; k++) xi[k] = x[i * IN + k];
    float es[H], ed[H];
#pragma unroll
    for (int h = 0; h < H; h++) { es[h] = 0.f; ed[h] = 0.f; }
#pragma unroll
    for (int hc = 0; hc < HC; hc++) {
        float acc = 0.f;
#pragma unroll
        for (int k = 0; k < IN; k++) acc += xi[k] * sW[k * HC + hc];
        g_h[i * HC + hc] = acc;
        es[hc / 4] += acc * sas[hc];
        ed[hc / 4] += acc * sad[hc];
    }
#pragma unroll
    for (int h = 0; h < H; h++) {
        g_es[i * H + h] = es[h];
        g_ed[i * H + h] = ed[h];
    }
}

// ---------------- warp-per-node single-pass softmax aggregate ----------------
// exp without max-shift (values O(1)): mathematically identical to the
// reference's max-shifted segment softmax.
template <int L>
__global__ void k_aggregate(const float* __restrict__ bias) {
    constexpr int H  = (L == 1) ? 8 : (L == 2) ? 4 : 2;
    constexpr int HC = H * 4;
    float* out = (L == 1) ? g_x3 : (L == 2) ? g_x4 : g_x6;   // device-side symbol ref

    int gt = blockIdx.x * blockDim.x + threadIdx.x;
    int node = gt >> 5;
    int lane = gt & 31;
    if (node >= NN) return;
    int beg = g_off[node], end = g_off[node + 1];

    float edv[H];
#pragma unroll
    for (int h = 0; h < H; h++) edv[h] = g_ed[node * H + h];

    float denom[H];
    float acc[HC];
#pragma unroll
    for (int h = 0; h < H; h++) denom[h] = 0.f;
#pragma unroll
    for (int j = 0; j < HC; j++) acc[j] = 0.f;

    for (int e = beg + lane; e < end; e += 32) {
        int s = g_srclist[e];
        const float4* hp = (const float4*)&g_h[s * HC];
#pragma unroll
        for (int h = 0; h < H; h++) {
            float v = g_es[s * H + h] + edv[h];
            v = v > 0.f ? v : 0.2f * v;        // leaky relu
            float ex = expf(v);
            denom[h] += ex;
            float4 hv = hp[h];
            acc[h * 4 + 0] += ex * hv.x;
            acc[h * 4 + 1] += ex * hv.y;
            acc[h * 4 + 2] += ex * hv.z;
            acc[h * 4 + 3] += ex * hv.w;
        }
    }

#pragma unroll
    for (int h = 0; h < H; h++)
#pragma unroll
        for (int o = 16; o; o >>= 1) denom[h] += __shfl_xor_sync(0xffffffffu, denom[h], o);
#pragma unroll
    for (int j = 0; j < HC; j++)
#pragma unroll
        for (int o = 16; o; o >>= 1) acc[j] += __shfl_xor_sync(0xffffffffu, acc[j], o);

#pragma unroll
    for (int j = 0; j < HC; j++) {
        if (lane == j) {
            float v = acc[j] / denom[j / 4] + bias[j];
            out[node * HC + j] = v > 0.f ? v : 0.f;    // relu
        }
    }
}

// ---------------- final scoring: bitmap-dedup adjacency ----------------
__global__ void k_clearbitmap() {
    const size_t W = ((size_t)NN * NN) / 32;
    size_t i = (size_t)(blockIdx.x * blockDim.x + threadIdx.x) * 4;
    if (i + 3 < W) *(uint4*)&g_bitmap[i] = make_uint4(0, 0, 0, 0);
    else for (size_t j = i; j < W; j++) g_bitmap[j] = 0u;
}

__global__ void k_initfinal() {
    int i = blockIdx.x * blockDim.x + threadIdx.x;
    if (i >= NN) return;
    g_degc[i] = 1;
#pragma unroll
    for (int c = 0; c < 8; c++) g_agg[i * 8 + c] = g_x6[i * 8 + c];  // diag
    size_t bit = (size_t)i * NN + i;
    g_bitmap[bit >> 5] = 1u << (bit & 31);   // diag bits: >32 bits apart, no word sharing
}

__global__ void k_dedup(int E) {
    int e = blockIdx.x * blockDim.x + threadIdx.x;
    if (e >= E) return;
    int r = g_rows[e], c = g_cols[e];
    size_t bit = (size_t)r * NN + c;
    unsigned mask = 1u << (bit & 31);
    unsigned old = atomicOr(&g_bitmap[bit >> 5], mask);
    if (!(old & mask)) {
        atomicAdd(&g_degc[r], 1);
        const float4* xp = (const float4*)&g_x6[c * 8];
        float4 a = xp[0], b = xp[1];
        atomicAdd(&g_agg[r * 8 + 0], a.x);
        atomicAdd(&g_agg[r * 8 + 1], a.y);
        atomicAdd(&g_agg[r * 8 + 2], a.z);
        atomicAdd(&g_agg[r * 8 + 3], a.w);
        atomicAdd(&g_agg[r * 8 + 4], b.x);
        atomicAdd(&g_agg[r * 8 + 5], b.y);
        atomicAdd(&g_agg[r * 8 + 6], b.z);
        atomicAdd(&g_agg[r * 8 + 7], b.w);
    }
}

__global__ void k_final(const float* __restrict__ x1,
                        const float* __restrict__ lin2w,
                        float* __restrict__ out) {
    int i = blockIdx.x * blockDim.x + threadIdx.x;
    if (i >= NN) return;
    float inv = 1.0f / (float)g_degc[i];       // row-normalized adj entry
    float r2 = 0.f, gl = 0.f;
#pragma unroll
    for (int c = 0; c < 8; c++) {
        float a = g_agg[i * 8 + c];            // sum of x6 over distinct nbrs + self
        r2 += g_x6[i * 8 + c] * a;             // <x6_i, sum_j x6_j>
        gl += (inv * a) * lin2w[c];            // (adj@x6) @ lin2_w
    }
    out[i] = r2 * inv + x1[i * 10] + gl;
}

// ---------------- host diag scratch ----------------
static float hdiag[NN * 32];

static double hmean(const void* sym, int n) {
    cudaMemcpyFromSymbol(hdiag, sym, (size_t)n * 4);
    double s = 0;
    for (int i = 0; i < n; i++) s += hdiag[i];
    return s / n;
}

// ---------------- launch ----------------
extern "C" void kernel_launch(void* const* d_in, const int* in_sizes, int n_in,
                              void* d_out, int out_size) {
    const float* x1    = (const float*)d_in[0];
    const void*  eidx  = d_in[2];
    const float* W1    = (const float*)d_in[4];
    const float* as1   = (const float*)d_in[5];
    const float* ad1   = (const float*)d_in[6];
    const float* b1    = (const float*)d_in[7];
    const float* W2    = (const float*)d_in[8];
    const float* as2   = (const float*)d_in[9];
    const float* ad2   = (const float*)d_in[10];
    const float* b2    = (const float*)d_in[11];
    const float* W3    = (const float*)d_in[12];
    const float* as3   = (const float*)d_in[13];
    const float* ad3   = (const float*)d_in[14];
    const float* b3    = (const float*)d_in[15];
    const float* lin2w = (const float*)d_in[16];
    float* out = (float*)d_out;

    int E = in_sizes[2] / 2;
    if (E > EMAX) E = EMAX;

    const int TB = 256;
    int gN  = (NN + TB - 1) / TB;
    int gE  = (E + TB - 1) / TB;
    int gEN = (E + NN + TB - 1) / TB;
    int gW  = (NN * 32 + TB - 1) / TB;

    // edge decode + CSR build
    k_detect<<<1, 1>>>(eidx);
    k_decode<<<gE, TB>>>(eidx, E);
    k_initdeg<<<gN, TB>>>();
    k_hist<<<gE, TB>>>(E);
    k_scan<<<1, 1024>>>();
    k_scatter<<<gEN, TB>>>(E);

    // GAT layers (all inter-layer state via device symbols inside kernels)
    k_transform<1><<<gN, TB>>>(x1, W1, as1, ad1);
    k_aggregate<1><<<gW, TB>>>(b1);
    k_transform<2><<<gN, TB>>>(nullptr, W2, as2, ad2);
    k_aggregate<2><<<gW, TB>>>(b2);
    k_transform<3><<<gN, TB>>>(nullptr, W3, as3, ad3);
    k_aggregate<3><<<gW, TB>>>(b3);

    // final scoring
    {
        const size_t Wd = ((size_t)NN * NN) / 32;
        int gB = (int)(((Wd + 3) / 4 + TB - 1) / TB);
        k_clearbitmap<<<gB, TB>>>();
    }
    k_initfinal<<<gN, TB>>>();
    k_dedup<<<gE, TB>>>(E);
    k_final<<<gN, TB>>>(x1, lin2w, out);

    // ---- capture-safe tripwire: verify pipeline is live on non-capture calls ----
    cudaStreamCaptureStatus st1 = cudaStreamCaptureStatusActive;
    cudaStreamCaptureStatus st2 = cudaStreamCaptureStatusActive;
    bool q1 = (cudaStreamIsCapturing(cudaStreamPerThread, &st1) == cudaSuccess);
    bool q2 = (cudaStreamIsCapturing(cudaStreamLegacy, &st2) == cudaSuccess);
    bool capturing = !(q1 && q2 && st1 == cudaStreamCaptureStatusNone &&
                       st2 == cudaStreamCaptureStatusNone);
    if (!capturing) {
        if (cudaDeviceSynchronize() == cudaSuccess) {
            double mh  = hmean(g_h,  NN * 8);
            double m3  = hmean(g_x3, NN * 32);
            double m4  = hmean(g_x4, NN * 16);
            double m6  = hmean(g_x6, NN * 8);
            double ma  = hmean(g_agg, NN * 8);
            if (!(m6 > 1e-9 || m6 < -1e-9)) {   // pipeline dead (or NaN) -> report & abort
                fprintf(stderr,
                        "ZTRIP hmean=%.6e x3mean=%.6e x4mean=%.6e x6mean=%.6e aggmean=%.6e\n",
                        mh, m3, m4, m6, ma);
                fflush(stderr);
                exit(1);
            }
        }
    }
}